// round 9
// baseline (speedup 1.0000x reference)
#include <cuda_runtime.h>
#include <math.h>

// Problem constants (fixed by the dataset)
#define B_    256
#define S_    196
#define RNN_  1024
#define ATTH_ 512
#define NSPLIT 7
#define SCHUNK 28   // 196 / 7
#define KSPLIT 16   // k1 split-k factor

// Scratch (allocation-free: __device__ globals)
__device__ float g_att_h_part[KSPLIT * B_ * ATTH_];  // 8 MB  (k1 partials)
__device__ float g_scores[B_ * S_];                  // 200 KB
__device__ float g_part[NSPLIT * B_ * RNN_];         // 7 MB  (k3 partials)
__device__ int   g_cnt[B_];                          // per-batch tickets (zero-init)

// ---------------------------------------------------------------------------
// HW tanh: MUFU.TANH (abs err ~5e-4; output rel err measured ~3e-6, gate 1e-3)
// ---------------------------------------------------------------------------
__device__ __forceinline__ float tanh_approx(float x)
{
    float y;
    asm("tanh.approx.f32 %0, %1;" : "=f"(y) : "f"(x));
    return y;
}

// ---------------------------------------------------------------------------
// K1: partial att_h: part[kz][b][a] = sum_{k in chunk kz} h[b,k] * W[a,k]
// 64x64 tile, BK=32, 4x4 microtile, double-buffered smem, split-k=16.
// grid = (8, 4, 16) = 512 blocks (~3.5/SM -> enough warps to cover LDS lat).
// ---------------------------------------------------------------------------
__global__ __launch_bounds__(256) void k1_h2att(
    const float* __restrict__ h, const float* __restrict__ w,
    float* __restrict__ part)
{
    __shared__ float sh[2][32][68];   // [buf][k][b]
    __shared__ float sw[2][32][68];   // [buf][k][a]

    const int t  = threadIdx.x;
    const int a0 = blockIdx.x * 64;
    const int b0 = blockIdx.y * 64;
    const int kz = blockIdx.z;
    const int tx = t & 15;            // a-dim (x4)
    const int ty = t >> 4;            // b-dim (x4)

    const int lr = t >> 3;            // 0..31
    const int lc = (t & 7) * 4;       // 0,4,..,28

    const size_t kbase = (size_t)kz * (RNN_ / KSPLIT);
    const float* h0 = &h[(size_t)(b0 + lr) * RNN_ + kbase + lc];
    const float* h1 = &h[(size_t)(b0 + lr + 32) * RNN_ + kbase + lc];
    const float* w0 = &w[(size_t)(a0 + lr) * RNN_ + kbase + lc];
    const float* w1 = &w[(size_t)(a0 + lr + 32) * RNN_ + kbase + lc];

    float4 hA = *(const float4*)h0;
    float4 hB = *(const float4*)h1;
    float4 wA = *(const float4*)w0;
    float4 wB = *(const float4*)w1;
    #pragma unroll
    for (int c = 0; c < 4; c++) {
        sh[0][lc + c][lr]      = (&hA.x)[c];
        sh[0][lc + c][lr + 32] = (&hB.x)[c];
        sw[0][lc + c][lr]      = (&wA.x)[c];
        sw[0][lc + c][lr + 32] = (&wB.x)[c];
    }
    __syncthreads();

    float acc[4][4] = {};

    const int NT = RNN_ / KSPLIT / 32;   // 2 k-tiles
    #pragma unroll
    for (int kt = 0; kt < NT; kt++) {
        const int buf = kt & 1;
        if (kt + 1 < NT) {
            hA = *(const float4*)(h0 + (kt + 1) * 32);
            hB = *(const float4*)(h1 + (kt + 1) * 32);
            wA = *(const float4*)(w0 + (kt + 1) * 32);
            wB = *(const float4*)(w1 + (kt + 1) * 32);
        }
        #pragma unroll
        for (int kk = 0; kk < 32; kk++) {
            float4 hv = *(const float4*)&sh[buf][kk][ty * 4];
            float4 wv = *(const float4*)&sw[buf][kk][tx * 4];
            #pragma unroll
            for (int i = 0; i < 4; i++)
                #pragma unroll
                for (int j = 0; j < 4; j++)
                    acc[i][j] += (&hv.x)[i] * (&wv.x)[j];
        }
        __syncthreads();
        if (kt + 1 < NT) {
            const int nb = buf ^ 1;
            #pragma unroll
            for (int c = 0; c < 4; c++) {
                sh[nb][lc + c][lr]      = (&hA.x)[c];
                sh[nb][lc + c][lr + 32] = (&hB.x)[c];
                sw[nb][lc + c][lr]      = (&wA.x)[c];
                sw[nb][lc + c][lr + 32] = (&wB.x)[c];
            }
            __syncthreads();
        }
    }

    float* op = part + (size_t)kz * B_ * ATTH_;
    #pragma unroll
    for (int i = 0; i < 4; i++) {
        const int bb = b0 + ty * 4 + i;
        float4 r = make_float4(acc[i][0], acc[i][1], acc[i][2], acc[i][3]);
        *(float4*)&op[(size_t)bb * ATTH_ + a0 + tx * 4] = r;
    }
}

// ---------------------------------------------------------------------------
// helpers for k2a
// ---------------------------------------------------------------------------
__device__ __forceinline__ float row_score(
    const float4 v[4], const float4* __restrict__ ah4,
    const float4* __restrict__ wa4, int lane)
{
    float acc = 0.f;
    #pragma unroll
    for (int i = 0; i < 4; i++) {
        float4 a  = ah4[lane + i * 32];
        float4 wv = wa4[lane + i * 32];
        acc += tanh_approx(v[i].x + a.x) * wv.x + tanh_approx(v[i].y + a.y) * wv.y
             + tanh_approx(v[i].z + a.z) * wv.z + tanh_approx(v[i].w + a.w) * wv.w;
    }
    return acc;
}

__device__ __forceinline__ void load_row(
    float4 v[4], const float4* __restrict__ ps, int lane)
{
    v[0] = __ldcs(&ps[lane]);
    v[1] = __ldcs(&ps[lane + 32]);
    v[2] = __ldcs(&ps[lane + 64]);
    v[3] = __ldcs(&ps[lane + 96]);
}

// ---------------------------------------------------------------------------
// K2a: scores[b,s] = sum_a tanh(p[b,s,a] + att_h[b,a]) * w_alpha[a]
// att_h assembled in smem from the KSPLIT k1 partials + bias (L2-hot).
// grid = (B, 4), 256 threads; warp handles 3 row-pairs, software-pipelined.
// ---------------------------------------------------------------------------
__global__ __launch_bounds__(256) void k2a_scores(
    const float* __restrict__ p, const float* __restrict__ att_h_part,
    const float* __restrict__ bias, const float* __restrict__ w_alpha,
    float* __restrict__ scores)
{
    const int b     = blockIdx.x;
    const int chunk = blockIdx.y;
    const int t     = threadIdx.x;

    __shared__ float4 ah4[ATTH_ / 4];
    __shared__ float4 wa4[ATTH_ / 4];
    if (t < ATTH_ / 4) {
        float4 r = ((const float4*)bias)[t];
        #pragma unroll
        for (int kz = 0; kz < KSPLIT; kz++) {
            const float4 v = ((const float4*)(att_h_part
                + ((size_t)kz * B_ + b) * ATTH_))[t];
            r.x += v.x; r.y += v.y; r.z += v.z; r.w += v.w;
        }
        ah4[t] = r;
        wa4[t] = ((const float4*)w_alpha)[t];
    }
    __syncthreads();

    const int warp = t >> 5, lane = t & 31;
    const int s_lo = chunk * 49;
    const float4* pb = (const float4*)(p + (size_t)b * S_ * ATTH_);

    float4 curU[4], curQ[4], tailV[4];

    {
        const int s = s_lo + warp * 2;
        load_row(curU, pb + (size_t)s * (ATTH_ / 4), lane);
        load_row(curQ, pb + (size_t)(s + 1) * (ATTH_ / 4), lane);
    }
    if (warp == 0)
        load_row(tailV, pb + (size_t)(s_lo + 48) * (ATTH_ / 4), lane);

    #pragma unroll
    for (int it = 0; it < 3; it++) {
        const int s = s_lo + (warp + 8 * it) * 2;
        float4 nU[4], nQ[4];
        if (it < 2) {
            const int sn = s_lo + (warp + 8 * (it + 1)) * 2;
            load_row(nU, pb + (size_t)sn * (ATTH_ / 4), lane);
            load_row(nQ, pb + (size_t)(sn + 1) * (ATTH_ / 4), lane);
        }
        float accA = row_score(curU, ah4, wa4, lane);
        float accB = row_score(curQ, ah4, wa4, lane);
        #pragma unroll
        for (int o = 16; o; o >>= 1) {
            accA += __shfl_xor_sync(0xffffffffu, accA, o);
            accB += __shfl_xor_sync(0xffffffffu, accB, o);
        }
        if (lane == 0) {
            scores[(size_t)b * S_ + s]     = accA;
            scores[(size_t)b * S_ + s + 1] = accB;
        }
        if (it < 2) {
            #pragma unroll
            for (int i = 0; i < 4; i++) { curU[i] = nU[i]; curQ[i] = nQ[i]; }
        }
    }

    if (warp == 0) {
        float acc = row_score(tailV, ah4, wa4, lane);
        #pragma unroll
        for (int o = 16; o; o >>= 1)
            acc += __shfl_xor_sync(0xffffffffu, acc, o);
        if (lane == 0) scores[(size_t)b * S_ + s_lo + 48] = acc;
    }
}

// ---------------------------------------------------------------------------
// K3a: partial weighted sums with fused softmax + fused last-block reduce.
// Inner loop explicitly software-pipelined: 8 independent LDG.128 in flight.
// grid = (B, NSPLIT) = 1792 blocks, 128 threads; thread owns TWO float4 cols.
// ---------------------------------------------------------------------------
__global__ __launch_bounds__(128) void k3a_partial(
    const float* __restrict__ att, const float* __restrict__ scores,
    float* __restrict__ part, float* __restrict__ out)
{
    const int b     = blockIdx.x;
    const int split = blockIdx.y;
    const int t     = threadIdx.x;
    const int s_lo  = split * SCHUNK;

    __shared__ float es[S_];
    __shared__ float red[128];
    __shared__ float w_s[SCHUNK];
    __shared__ int   is_last;

    // --- inline softmax over scores[b, 0..195] (deterministic per block) ---
    float v0 = (t < S_)       ? scores[(size_t)b * S_ + t]       : -INFINITY;
    float v1 = (t + 128 < S_) ? scores[(size_t)b * S_ + t + 128] : -INFINITY;
    red[t] = fmaxf(v0, v1);
    __syncthreads();
    #pragma unroll
    for (int o = 64; o; o >>= 1) {
        if (t < o) red[t] = fmaxf(red[t], red[t + o]);
        __syncthreads();
    }
    const float m = red[0];
    __syncthreads();
    float e0 = (t < S_)       ? __expf(v0 - m) : 0.f;
    float e1 = (t + 128 < S_) ? __expf(v1 - m) : 0.f;
    if (t < S_)       es[t]       = e0;
    if (t + 128 < S_) es[t + 128] = e1;
    red[t] = e0 + e1;
    __syncthreads();
    #pragma unroll
    for (int o = 64; o; o >>= 1) {
        if (t < o) red[t] += red[t + o];
        __syncthreads();
    }
    const float inv = 1.f / red[0];
    __syncthreads();
    if (t < SCHUNK) w_s[t] = es[s_lo + t] * inv;
    __syncthreads();

    // --- weighted partial sum, 2 cols/thread, pipelined 2 s-steps deep ---
    const float4* ap = (const float4*)(att + ((size_t)b * S_ + s_lo) * RNN_);
    float4 acc0 = make_float4(0.f, 0.f, 0.f, 0.f);
    float4 acc1 = make_float4(0.f, 0.f, 0.f, 0.f);

    float4 a0 = __ldcs(&ap[t]);
    float4 b0v = __ldcs(&ap[t + 128]);
    float4 a1 = __ldcs(&ap[(RNN_ / 4) + t]);
    float4 b1v = __ldcs(&ap[(RNN_ / 4) + t + 128]);

    #pragma unroll
    for (int s = 0; s < SCHUNK; s += 2) {
        float4 na0, nb0, na1, nb1;
        if (s + 2 < SCHUNK) {
            na0 = __ldcs(&ap[(size_t)(s + 2) * (RNN_ / 4) + t]);
            nb0 = __ldcs(&ap[(size_t)(s + 2) * (RNN_ / 4) + t + 128]);
            na1 = __ldcs(&ap[(size_t)(s + 3) * (RNN_ / 4) + t]);
            nb1 = __ldcs(&ap[(size_t)(s + 3) * (RNN_ / 4) + t + 128]);
        }
        const float w0 = w_s[s], w1 = w_s[s + 1];
        acc0.x += w0 * a0.x;  acc0.y += w0 * a0.y;
        acc0.z += w0 * a0.z;  acc0.w += w0 * a0.w;
        acc1.x += w0 * b0v.x; acc1.y += w0 * b0v.y;
        acc1.z += w0 * b0v.z; acc1.w += w0 * b0v.w;
        acc0.x += w1 * a1.x;  acc0.y += w1 * a1.y;
        acc0.z += w1 * a1.z;  acc0.w += w1 * a1.w;
        acc1.x += w1 * b1v.x; acc1.y += w1 * b1v.y;
        acc1.z += w1 * b1v.z; acc1.w += w1 * b1v.w;
        if (s + 2 < SCHUNK) {
            a0 = na0; b0v = nb0; a1 = na1; b1v = nb1;
        }
    }

    float4* op = (float4*)(part + ((size_t)split * B_ + b) * RNN_);
    op[t]       = acc0;
    op[t + 128] = acc1;

    // --- last-block-per-batch final reduction (threadfence pattern) ---
    __threadfence();
    __syncthreads();
    if (t == 0) {
        int ticket = atomicAdd(&g_cnt[b], 1);
        is_last = (ticket == NSPLIT - 1) ? 1 : 0;
        if (is_last) g_cnt[b] = 0;   // reset for next graph replay
    }
    __syncthreads();

    if (is_last) {
        float4* ob = (float4*)(out + (size_t)b * RNN_);
        #pragma unroll
        for (int j = 0; j < 2; j++) {
            const int c4 = t + j * 128;   // float4 column 0..255
            float4 r = make_float4(0.f, 0.f, 0.f, 0.f);
            #pragma unroll
            for (int sp = 0; sp < NSPLIT; sp++) {
                const float4 v = __ldcg(
                    (const float4*)(part + ((size_t)sp * B_ + b) * RNN_) + c4);
                r.x += v.x; r.y += v.y; r.z += v.z; r.w += v.w;
            }
            ob[c4] = r;
        }
    }
}

// ---------------------------------------------------------------------------
extern "C" void kernel_launch(void* const* d_in, const int* in_sizes, int n_in,
                              void* d_out, int out_size)
{
    const float* h        = (const float*)d_in[0];  // [B, RNN]
    const float* att      = (const float*)d_in[1];  // [B, S, RNN]
    const float* p        = (const float*)d_in[2];  // [B, S, ATTH]
    const float* w_h2att  = (const float*)d_in[3];  // [ATTH, RNN]
    const float* b_h2att  = (const float*)d_in[4];  // [ATTH]
    const float* w_alpha  = (const float*)d_in[5];  // [1, ATTH]
    // d_in[6] = b_alpha: softmax-invariant, unused
    float* out = (float*)d_out;                     // [B, RNN]

    float *ahp_ptr = nullptr, *sc_ptr = nullptr, *part_ptr = nullptr;
    cudaGetSymbolAddress((void**)&ahp_ptr,  g_att_h_part);
    cudaGetSymbolAddress((void**)&sc_ptr,   g_scores);
    cudaGetSymbolAddress((void**)&part_ptr, g_part);

    k1_h2att<<<dim3(ATTH_ / 64, B_ / 64, KSPLIT), 256>>>(h, w_h2att, ahp_ptr);
    k2a_scores<<<dim3(B_, 4), 256>>>(p, ahp_ptr, b_h2att, w_alpha, sc_ptr);
    k3a_partial<<<dim3(B_, NSPLIT), 128>>>(att, sc_ptr, part_ptr, out);
}

// round 10
// speedup vs baseline: 1.1124x; 1.1124x over previous
#include <cuda_runtime.h>
#include <math.h>

// Problem constants (fixed by the dataset)
#define B_    256
#define S_    196
#define RNN_  1024
#define ATTH_ 512
#define NSPLIT 4
#define SCHUNK 49   // 196 / 4
#define KSPLIT 8    // k1 split-k factor

// Scratch (allocation-free: __device__ globals; zero-initialized)
__device__ float g_att_h_part[KSPLIT * B_ * ATTH_];  // 4 MB (k1 partials)
__device__ float g_scores[B_ * S_];                  // 200 KB
__device__ float g_part[NSPLIT * B_ * RNN_];         // 4 MB (k3 partials)
__device__ int   g_rdy[B_];                          // per-batch score tickets
__device__ int   g_cnt[B_];                          // per-batch partial tickets

// ---------------------------------------------------------------------------
// HW tanh: MUFU.TANH (abs err ~5e-4; measured output rel err ~3e-6, gate 1e-3)
// ---------------------------------------------------------------------------
__device__ __forceinline__ float tanh_approx(float x)
{
    float y;
    asm("tanh.approx.f32 %0, %1;" : "=f"(y) : "f"(x));
    return y;
}

// ---------------------------------------------------------------------------
// K1: partial att_h: part[kz][b][a] = sum_{k in chunk kz} h[b,k] * W[a,k]
// 64x64 tile, BK=32, 4x4 microtile, double-buffered smem, split-k=8.
// grid = (8, 4, 8) = 256 blocks, 256 threads.
// ---------------------------------------------------------------------------
__global__ __launch_bounds__(256) void k1_h2att(
    const float* __restrict__ h, const float* __restrict__ w,
    float* __restrict__ part)
{
    __shared__ float sh[2][32][68];
    __shared__ float sw[2][32][68];

    const int t  = threadIdx.x;
    const int a0 = blockIdx.x * 64;
    const int b0 = blockIdx.y * 64;
    const int kz = blockIdx.z;
    const int tx = t & 15;
    const int ty = t >> 4;
    const int lr = t >> 3;
    const int lc = (t & 7) * 4;

    const size_t kbase = (size_t)kz * (RNN_ / KSPLIT);
    const float* h0 = &h[(size_t)(b0 + lr) * RNN_ + kbase + lc];
    const float* h1 = &h[(size_t)(b0 + lr + 32) * RNN_ + kbase + lc];
    const float* w0 = &w[(size_t)(a0 + lr) * RNN_ + kbase + lc];
    const float* w1 = &w[(size_t)(a0 + lr + 32) * RNN_ + kbase + lc];

    float4 hA = *(const float4*)h0;
    float4 hB = *(const float4*)h1;
    float4 wA = *(const float4*)w0;
    float4 wB = *(const float4*)w1;
    #pragma unroll
    for (int c = 0; c < 4; c++) {
        sh[0][lc + c][lr]      = (&hA.x)[c];
        sh[0][lc + c][lr + 32] = (&hB.x)[c];
        sw[0][lc + c][lr]      = (&wA.x)[c];
        sw[0][lc + c][lr + 32] = (&wB.x)[c];
    }
    __syncthreads();

    float acc[4][4] = {};

    const int NT = RNN_ / KSPLIT / 32;   // 4 k-tiles
    #pragma unroll
    for (int kt = 0; kt < NT; kt++) {
        const int buf = kt & 1;
        if (kt + 1 < NT) {
            hA = *(const float4*)(h0 + (kt + 1) * 32);
            hB = *(const float4*)(h1 + (kt + 1) * 32);
            wA = *(const float4*)(w0 + (kt + 1) * 32);
            wB = *(const float4*)(w1 + (kt + 1) * 32);
        }
        #pragma unroll
        for (int kk = 0; kk < 32; kk++) {
            float4 hv = *(const float4*)&sh[buf][kk][ty * 4];
            float4 wv = *(const float4*)&sw[buf][kk][tx * 4];
            #pragma unroll
            for (int i = 0; i < 4; i++)
                #pragma unroll
                for (int j = 0; j < 4; j++)
                    acc[i][j] += (&hv.x)[i] * (&wv.x)[j];
        }
        __syncthreads();
        if (kt + 1 < NT) {
            const int nb = buf ^ 1;
            #pragma unroll
            for (int c = 0; c < 4; c++) {
                sh[nb][lc + c][lr]      = (&hA.x)[c];
                sh[nb][lc + c][lr + 32] = (&hB.x)[c];
                sw[nb][lc + c][lr]      = (&wA.x)[c];
                sw[nb][lc + c][lr + 32] = (&wB.x)[c];
            }
            __syncthreads();
        }
    }

    float* op = part + (size_t)kz * B_ * ATTH_;
    #pragma unroll
    for (int i = 0; i < 4; i++) {
        const int bb = b0 + ty * 4 + i;
        float4 r = make_float4(acc[i][0], acc[i][1], acc[i][2], acc[i][3]);
        *(float4*)&op[(size_t)bb * ATTH_ + a0 + tx * 4] = r;
    }
}

// ---------------------------------------------------------------------------
// helpers
// ---------------------------------------------------------------------------
__device__ __forceinline__ float row_score(
    const float4 v[4], const float4* __restrict__ ah4,
    const float4* __restrict__ wa4, int lane)
{
    float acc = 0.f;
    #pragma unroll
    for (int i = 0; i < 4; i++) {
        float4 a  = ah4[lane + i * 32];
        float4 wv = wa4[lane + i * 32];
        acc += tanh_approx(v[i].x + a.x) * wv.x + tanh_approx(v[i].y + a.y) * wv.y
             + tanh_approx(v[i].z + a.z) * wv.z + tanh_approx(v[i].w + a.w) * wv.w;
    }
    return acc;
}

__device__ __forceinline__ void load_row(
    float4 v[4], const float4* __restrict__ ps, int lane)
{
    v[0] = __ldcs(&ps[lane]);
    v[1] = __ldcs(&ps[lane + 32]);
    v[2] = __ldcs(&ps[lane + 64]);
    v[3] = __ldcs(&ps[lane + 96]);
}

// ---------------------------------------------------------------------------
// K23: fused scores + softmax + weighted sum with per-batch handoff.
// grid = (NSPLIT, B_) = (4, 256) -- split-major so each batch's 4 blocks are
// CONTIGUOUS in dispatch order (no-deadlock even under partial residency).
// 128 threads; __launch_bounds__(128, 8) keeps all ~1024 blocks resident.
//
// Phase A (producer): block (i, b) computes scores[b, 49i .. 49i+48].
// Handoff: threadfence + ticket; spin until all 4 chunks of batch b ready.
// Phase B (consumer): softmax over 196 scores (deterministic, recomputed per
// block), weighted partial sum over own 49 s-rows; last block reduces the 4
// partials and writes out[b,:], then resets tickets for graph replay.
// ---------------------------------------------------------------------------
__global__ __launch_bounds__(128, 8) void k23_fused(
    const float* __restrict__ p, const float* __restrict__ att_h_part,
    const float* __restrict__ bias, const float* __restrict__ w_alpha,
    const float* __restrict__ att, float* __restrict__ scores,
    float* __restrict__ part, float* __restrict__ out)
{
    const int split = blockIdx.x;
    const int b     = blockIdx.y;
    const int t     = threadIdx.x;
    const int warp  = t >> 5, lane = t & 31;
    const int s_lo  = split * SCHUNK;

    __shared__ float4 ah4[ATTH_ / 4];
    __shared__ float4 wa4[ATTH_ / 4];
    __shared__ float  es[S_];
    __shared__ float  red[128];
    __shared__ float  w_s[SCHUNK];
    __shared__ int    is_last;

    // --- assemble att_h[b,:] from k1 partials + bias (L2-hot) ---
    {
        float4 r = ((const float4*)bias)[t];
        #pragma unroll
        for (int kz = 0; kz < KSPLIT; kz++) {
            const float4 v = ((const float4*)(att_h_part
                + ((size_t)kz * B_ + b) * ATTH_))[t];
            r.x += v.x; r.y += v.y; r.z += v.z; r.w += v.w;
        }
        ah4[t] = r;
        wa4[t] = ((const float4*)w_alpha)[t];
    }
    __syncthreads();

    // --- Phase A: scores for own 49 rows (warp-per-row, pipelined) ---
    const float4* pb = (const float4*)(p + (size_t)b * S_ * ATTH_);
    {
        int r = warp;                       // warp 0: rows 0,4,..,48 (13)
        float4 cur[4];
        load_row(cur, pb + (size_t)(s_lo + r) * (ATTH_ / 4), lane);
        while (r < SCHUNK) {
            const int rn = r + 4;
            float4 nxt[4];
            if (rn < SCHUNK)
                load_row(nxt, pb + (size_t)(s_lo + rn) * (ATTH_ / 4), lane);
            float acc = row_score(cur, ah4, wa4, lane);
            #pragma unroll
            for (int o = 16; o; o >>= 1)
                acc += __shfl_xor_sync(0xffffffffu, acc, o);
            if (lane == 0) scores[(size_t)b * S_ + s_lo + r] = acc;
            if (rn < SCHUNK) {
                #pragma unroll
                for (int i = 0; i < 4; i++) cur[i] = nxt[i];
            }
            r = rn;
        }
    }

    // --- handoff: publish own chunk, wait for all 4 chunks of batch b ---
    __threadfence();
    __syncthreads();
    if (t == 0) {
        atomicAdd(&g_rdy[b], 1);
        while (((volatile int*)g_rdy)[b] < NSPLIT) { }
    }
    __syncthreads();
    __threadfence();

    // --- Phase B: softmax over scores[b, 0..195] (L2 reads, deterministic) ---
    float v0 = __ldcg(&scores[(size_t)b * S_ + t]);
    float v1 = (t + 128 < S_) ? __ldcg(&scores[(size_t)b * S_ + t + 128]) : -INFINITY;
    red[t] = fmaxf(v0, v1);
    __syncthreads();
    #pragma unroll
    for (int o = 64; o; o >>= 1) {
        if (t < o) red[t] = fmaxf(red[t], red[t + o]);
        __syncthreads();
    }
    const float m = red[0];
    __syncthreads();
    float e0 = __expf(v0 - m);
    float e1 = (t + 128 < S_) ? __expf(v1 - m) : 0.f;
    es[t] = e0;
    if (t + 128 < S_) es[t + 128] = e1;
    red[t] = e0 + e1;
    __syncthreads();
    #pragma unroll
    for (int o = 64; o; o >>= 1) {
        if (t < o) red[t] += red[t + o];
        __syncthreads();
    }
    const float inv = 1.f / red[0];
    __syncthreads();
    if (t < SCHUNK) w_s[t] = es[s_lo + t] * inv;
    __syncthreads();

    // --- weighted partial sum over own 49 rows, 2 float4 cols per thread ---
    const float4* ap = (const float4*)(att + ((size_t)b * S_ + s_lo) * RNN_);
    float4 acc0 = make_float4(0.f, 0.f, 0.f, 0.f);
    float4 acc1 = make_float4(0.f, 0.f, 0.f, 0.f);

    float4 cA = __ldcs(&ap[t]);
    float4 cB = __ldcs(&ap[t + 128]);
    for (int s = 0; s < SCHUNK; s++) {
        float4 nA, nB;
        if (s + 1 < SCHUNK) {
            nA = __ldcs(&ap[(size_t)(s + 1) * (RNN_ / 4) + t]);
            nB = __ldcs(&ap[(size_t)(s + 1) * (RNN_ / 4) + t + 128]);
        }
        const float w = w_s[s];
        acc0.x += w * cA.x; acc0.y += w * cA.y;
        acc0.z += w * cA.z; acc0.w += w * cA.w;
        acc1.x += w * cB.x; acc1.y += w * cB.y;
        acc1.z += w * cB.z; acc1.w += w * cB.w;
        if (s + 1 < SCHUNK) { cA = nA; cB = nB; }
    }

    float4* op = (float4*)(part + ((size_t)split * B_ + b) * RNN_);
    op[t]       = acc0;
    op[t + 128] = acc1;

    // --- last-block-per-batch: reduce 4 partials -> out, reset tickets ---
    __threadfence();
    __syncthreads();
    if (t == 0) {
        int ticket = atomicAdd(&g_cnt[b], 1);
        is_last = (ticket == NSPLIT - 1) ? 1 : 0;
        if (is_last) { g_cnt[b] = 0; g_rdy[b] = 0; }   // graph-replay reset
    }
    __syncthreads();

    if (is_last) {
        float4* ob = (float4*)(out + (size_t)b * RNN_);
        #pragma unroll
        for (int j = 0; j < 2; j++) {
            const int c4 = t + j * 128;
            float4 r = make_float4(0.f, 0.f, 0.f, 0.f);
            #pragma unroll
            for (int sp = 0; sp < NSPLIT; sp++) {
                const float4 v = __ldcg(
                    (const float4*)(part + ((size_t)sp * B_ + b) * RNN_) + c4);
                r.x += v.x; r.y += v.y; r.z += v.z; r.w += v.w;
            }
            ob[c4] = r;
        }
    }
}

// ---------------------------------------------------------------------------
extern "C" void kernel_launch(void* const* d_in, const int* in_sizes, int n_in,
                              void* d_out, int out_size)
{
    const float* h        = (const float*)d_in[0];  // [B, RNN]
    const float* att      = (const float*)d_in[1];  // [B, S, RNN]
    const float* p        = (const float*)d_in[2];  // [B, S, ATTH]
    const float* w_h2att  = (const float*)d_in[3];  // [ATTH, RNN]
    const float* b_h2att  = (const float*)d_in[4];  // [ATTH]
    const float* w_alpha  = (const float*)d_in[5];  // [1, ATTH]
    // d_in[6] = b_alpha: softmax-invariant, unused
    float* out = (float*)d_out;                     // [B, RNN]

    float *ahp_ptr = nullptr, *sc_ptr = nullptr, *part_ptr = nullptr;
    cudaGetSymbolAddress((void**)&ahp_ptr,  g_att_h_part);
    cudaGetSymbolAddress((void**)&sc_ptr,   g_scores);
    cudaGetSymbolAddress((void**)&part_ptr, g_part);

    k1_h2att<<<dim3(ATTH_ / 64, B_ / 64, KSPLIT), 256>>>(h, w_h2att, ahp_ptr);
    k23_fused<<<dim3(NSPLIT, B_), 128>>>(p, ahp_ptr, b_h2att, w_alpha,
                                         att, sc_ptr, part_ptr, out);
}